// round 1
// baseline (speedup 1.0000x reference)
#include <cuda_runtime.h>
#include <cstdint>

// SphConv: out[b,o,k] = (scale_l/128) * sum_i x[b,i,k] * w[o,i,l(k)/2]
// B=16384, C_IN=C_OUT=128, N_COEFFS=45, l in {0,2,4,6,8}
// Per-l GEMM: C[o, (b,k)] = Wl[o,i] @ X[i,(b,k)], M=K=128, N=16384*(2l+1)

#define CI 128
#define CO 128
#define NC 45
#define BSTRIDE (CI * NC)   // 5760 floats per b (both x and out)

typedef unsigned long long ull;
struct __align__(16) ull2_t { ull x, y; };

// Weights transposed + scale-folded: wt[l2][i][o], 5*128*128 floats = 320 KB
__device__ float g_wt[5 * 128 * 128];

__global__ void wt_transpose_kernel(const float* __restrict__ w) {
    int idx = blockIdx.x * blockDim.x + threadIdx.x;   // 81920 threads exactly
    int l2  = idx >> 14;
    int rem = idx & 16383;
    int i   = rem >> 7;
    int o   = rem & 127;
    float l = 2.0f * (float)l2;
    // scale = 2*pi*sqrt(4*pi/(2l+1)) / 128
    float s = 6.28318530717958647692f *
              sqrtf(12.5663706143591729539f / (2.0f * l + 1.0f)) * (1.0f / 128.0f);
    g_wt[idx] = w[(o * 128 + i) * 5 + l2] * s;
}

// One CTA = 128 output rows (o) x 128 fused (b,k) columns, K=128 in 4 chunks of 32.
// 256 threads, each computes an 8x8 register tile (split 4+4 CUTLASS-style),
// accumulated as 32 packed f32x2 pairs via fma.rn.f32x2 (2 MACs/op).
template <int NL, int KOFF, int L2>
__global__ __launch_bounds__(256, 2)
void sphconv_gemm(const float* __restrict__ x, float* __restrict__ out) {
    __shared__ __align__(16) float As[32][128];  // wt chunk: [i_local][o]
    __shared__ __align__(16) float Bs[32][128];  // x chunk:  [i_local][col]

    const int tid  = threadIdx.x;
    const int tile = blockIdx.x;
    const int tx   = tid & 15;   // column-group
    const int ty   = tid >> 4;   // row-group

    // ---- per-thread load column (each thread owns one of the 128 columns) ----
    const int loadcol = tid & 127;
    const int gcol    = tile * 128 + loadcol;
    const int lb      = gcol / NL;                 // batch index
    const int lk      = gcol - lb * NL + KOFF;     // coefficient index
    const float* xcol = x + (size_t)lb * BSTRIDE + lk;
    const int irow0   = tid >> 7;                  // 0 or 1: which i-parity to load

    const float4* wt4 = ((const float4*)g_wt) + L2 * 4096;

    ull accp[8][4];
    #pragma unroll
    for (int m = 0; m < 8; m++)
        #pragma unroll
        for (int p = 0; p < 4; p++) accp[m][p] = 0ull;

    #pragma unroll
    for (int ic = 0; ic < 4; ic++) {
        // load weight chunk (coalesced float4 from L2-hot g_wt)
        #pragma unroll
        for (int it = 0; it < 4; it++) {
            int idx4 = it * 256 + tid;            // 1024 float4 = 32x128 floats
            ((float4*)As)[idx4] = wt4[ic * 1024 + idx4];
        }
        // load x chunk: each thread fills its column for 16 i-rows
        #pragma unroll
        for (int it = 0; it < 16; it++) {
            int il = irow0 + it * 2;
            Bs[il][loadcol] = xcol[(ic * 32 + il) * NC];
        }
        __syncthreads();

        #pragma unroll
        for (int i = 0; i < 32; i++) {
            float4 a0 = *(const float4*)&As[i][ty * 4];
            float4 a1 = *(const float4*)&As[i][64 + ty * 4];
            ull2_t b0 = *(const ull2_t*)&Bs[i][tx * 4];
            ull2_t b1 = *(const ull2_t*)&Bs[i][64 + tx * 4];
            ull bp0 = b0.x, bp1 = b0.y, bp2 = b1.x, bp3 = b1.y;
            float av[8] = {a0.x, a0.y, a0.z, a0.w, a1.x, a1.y, a1.z, a1.w};
            #pragma unroll
            for (int m = 0; m < 8; m++) {
                ull ap;
                unsigned int au = __float_as_uint(av[m]);
                asm("mov.b64 %0, {%1, %1};" : "=l"(ap) : "r"(au));
                asm("fma.rn.f32x2 %0, %1, %2, %0;" : "+l"(accp[m][0]) : "l"(ap), "l"(bp0));
                asm("fma.rn.f32x2 %0, %1, %2, %0;" : "+l"(accp[m][1]) : "l"(ap), "l"(bp1));
                asm("fma.rn.f32x2 %0, %1, %2, %0;" : "+l"(accp[m][2]) : "l"(ap), "l"(bp2));
                asm("fma.rn.f32x2 %0, %1, %2, %0;" : "+l"(accp[m][3]) : "l"(ap), "l"(bp3));
            }
        }
        __syncthreads();
    }

    // ---- epilogue: scatter to out[b][o][k] ----
    int ro[8];
    #pragma unroll
    for (int m = 0; m < 8; m++) ro[m] = (m < 4) ? (ty * 4 + m) : (64 + ty * 4 + m - 4);

    #pragma unroll
    for (int g = 0; g < 2; g++) {
        #pragma unroll
        for (int pp = 0; pp < 2; pp++) {
            #pragma unroll
            for (int h = 0; h < 2; h++) {
                int coll = g * 64 + tx * 4 + pp * 2 + h;
                int col  = tile * 128 + coll;
                int b    = col / NL;
                int k    = col - b * NL + KOFF;
                float* ocol = out + (size_t)b * BSTRIDE + k;
                #pragma unroll
                for (int m = 0; m < 8; m++) {
                    ull v = accp[m][g * 2 + pp];
                    unsigned int bits = h ? (unsigned int)(v >> 32) : (unsigned int)v;
                    ocol[ro[m] * NC] = __uint_as_float(bits);
                }
            }
        }
    }
}

extern "C" void kernel_launch(void* const* d_in, const int* in_sizes, int n_in,
                              void* d_out, int out_size) {
    const float* x = (const float*)d_in[0];   // [16384, 128, 45] f32
    const float* w = (const float*)d_in[1];   // [128, 128, 5] f32
    float* out = (float*)d_out;               // [16384, 128, 45] f32

    wt_transpose_kernel<<<160, 512>>>(w);     // 81920 threads exactly

    // l-blocks: sizes {1,5,9,13,17}, k offsets {0,1,6,15,28}
    // tiles per l = 16384*NL/128 = 128*NL
    sphconv_gemm<1,  0,  0><<< 128, 256>>>(x, out);
    sphconv_gemm<5,  1,  1><<< 640, 256>>>(x, out);
    sphconv_gemm<9,  6,  2><<<1152, 256>>>(x, out);
    sphconv_gemm<13, 15, 3><<<1664, 256>>>(x, out);
    sphconv_gemm<17, 28, 4><<<2176, 256>>>(x, out);
}

// round 3
// speedup vs baseline: 1.2296x; 1.2296x over previous
#include <cuda_runtime.h>
#include <cuda_bf16.h>
#include <cstdint>

// SphConv via mma.sync (HMMA) bf16 split-precision GEMM.
// out[b,o,k] = (scale_l/128) * sum_i x[b,i,k] * w[o,i,l(k)/2]
// Per l-group GEMM: D[o, (b,k)] = W_l[o,i] @ X[i,(b,k)], M=K=128.
// Split bf16: D = Ah*Bh + Ah*Bl + Al*Bh (fp32 accum), rel err ~1e-5.

#define NCOEF 45
#define BSTRIDE (128 * NCOEF)

// smem layout in halves (__nv_bfloat16 units)
#define AS_STRIDE 136                  // 128 + 8 pad -> 272B rows, conflict-free
#define BS_STRIDE 40                   // 32 + 8 pad  -> 80B rows, conflict-free
#define AS_SIZE (128 * AS_STRIDE)      // 17408 halves
#define BS_SIZE (128 * BS_STRIDE)      // 5120 halves
#define SM_AH 0
#define SM_AL AS_SIZE
#define SM_B  (2 * AS_SIZE)            // [buf][prec][128][40]
#define SMEM_BYTES ((2 * AS_SIZE + 4 * BS_SIZE) * 2)   // 110592

// Split weights, scale folded: [l2][o][i] bf16
__device__ __nv_bfloat16 g_wh[5 * 128 * 128];
__device__ __nv_bfloat16 g_wl[5 * 128 * 128];

__global__ void prep_w(const float* __restrict__ w) {
    int idx = blockIdx.x * blockDim.x + threadIdx.x;  // 81920 exactly
    int l2 = idx >> 14;
    int rem = idx & 16383;
    int o = rem >> 7;
    int i = rem & 127;
    float l = 2.0f * (float)l2;
    float s = 6.28318530717958647692f *
              sqrtf(12.5663706143591729539f / (2.0f * l + 1.0f)) * (1.0f / 128.0f);
    float v = w[(o * 128 + i) * 5 + l2] * s;
    __nv_bfloat16 h = __float2bfloat16(v);
    g_wh[idx] = h;
    g_wl[idx] = __float2bfloat16(v - __bfloat162float(h));
}

__device__ __forceinline__ void mma_bf16(float* d, const uint32_t* a, const uint32_t* b) {
    asm volatile(
        "mma.sync.aligned.m16n8k16.row.col.f32.bf16.bf16.f32 "
        "{%0,%1,%2,%3}, {%4,%5,%6,%7}, {%8,%9}, {%0,%1,%2,%3};"
        : "+f"(d[0]), "+f"(d[1]), "+f"(d[2]), "+f"(d[3])
        : "r"(a[0]), "r"(a[1]), "r"(a[2]), "r"(a[3]), "r"(b[0]), "r"(b[1]));
}

template <int NL, int KOFF, int L2>
__device__ __forceinline__ void run_group(const float* __restrict__ x,
                                          float* __restrict__ out,
                                          int ctaIdx, __nv_bfloat16* sm) {
    const int tid  = threadIdx.x;
    const int lane = tid & 31;
    const int wid  = tid >> 5;
    const int wm   = wid & 1;          // m-half: 0/1 -> o offset 64*wm
    const int wn   = wid >> 1;         // n-quarter: 0..3 -> col offset 32*wn
    const int lr   = lane >> 2;        // 0..7 row-in-frag
    const int lc   = lane & 3;         // 0..3 col-group

    // ---- load resident A (hi/lo weights) into smem, once per CTA ----
    {
        const uint4* sh = (const uint4*)(g_wh + L2 * 16384);
        const uint4* sl = (const uint4*)(g_wl + L2 * 16384);
        #pragma unroll
        for (int it = 0; it < 8; it++) {
            int v4 = it * 256 + tid;           // 2048 uint4 total
            int r  = v4 >> 4, c8 = v4 & 15;    // row, 8-half group
            *(uint4*)(sm + SM_AH + r * AS_STRIDE + c8 * 8) = sh[v4];
            *(uint4*)(sm + SM_AL + r * AS_STRIDE + c8 * 8) = sl[v4];
        }
    }

    const int n  = tid & 127;          // column owned for B build
    const int hh = tid >> 7;           // which 16-row half of the chunk

    for (int tt = 0; tt < 4; tt++) {
        const int gtile = ctaIdx * 4 + tt;
        const int gn = gtile * 128 + n;
        const int b  = gn / NL;
        const int kk = gn - b * NL + KOFF;
        const float* xcol = x + (size_t)b * BSTRIDE + kk;

        float acc[4][4][4];
        #pragma unroll
        for (int mi = 0; mi < 4; mi++)
            #pragma unroll
            for (int ni = 0; ni < 4; ni++)
                #pragma unroll
                for (int q = 0; q < 4; q++) acc[mi][ni][q] = 0.0f;

        float v[16];
        // prefetch chunk 0
        #pragma unroll
        for (int j = 0; j < 16; j++) v[j] = xcol[(hh * 16 + j) * NCOEF];

        // convert + store chunk 0 into buf 0
        {
            __nv_bfloat16* bh = sm + SM_B + n * BS_STRIDE + hh * 16;
            __nv_bfloat16* bl = bh + BS_SIZE;
            uint32_t ph[8], pl[8];
            #pragma unroll
            for (int j = 0; j < 8; j++) {
                __nv_bfloat162 hp, lp;
                hp.x = __float2bfloat16(v[2 * j]);
                hp.y = __float2bfloat16(v[2 * j + 1]);
                lp.x = __float2bfloat16(v[2 * j] - __bfloat162float(hp.x));
                lp.y = __float2bfloat16(v[2 * j + 1] - __bfloat162float(hp.y));
                ph[j] = *(uint32_t*)&hp;
                pl[j] = *(uint32_t*)&lp;
            }
            *(uint4*)bh       = make_uint4(ph[0], ph[1], ph[2], ph[3]);
            *(uint4*)(bh + 8) = make_uint4(ph[4], ph[5], ph[6], ph[7]);
            *(uint4*)bl       = make_uint4(pl[0], pl[1], pl[2], pl[3]);
            *(uint4*)(bl + 8) = make_uint4(pl[4], pl[5], pl[6], pl[7]);
        }
        __syncthreads();

        #pragma unroll
        for (int c = 0; c < 4; c++) {
            // prefetch next chunk into regs (hidden under MMA)
            if (c < 3) {
                #pragma unroll
                for (int j = 0; j < 16; j++)
                    v[j] = xcol[((c + 1) * 32 + hh * 16 + j) * NCOEF];
            }

            // ---- MMA on buf c&1 ----
            const __nv_bfloat16* bbh = sm + SM_B + (c & 1) * (2 * BS_SIZE);
            const __nv_bfloat16* bbl = bbh + BS_SIZE;

            #pragma unroll
            for (int ks = 0; ks < 2; ks++) {
                const int kb = c * 32 + ks * 16;      // column in A
                const int kbb = ks * 16;              // column in B chunk
                uint32_t af[4][4], bhf[4][2], blf[4][2];

                #pragma unroll
                for (int mi = 0; mi < 4; mi++) {
                    const __nv_bfloat16* ap =
                        sm + SM_AH + (wm * 64 + mi * 16 + lr) * AS_STRIDE + kb + lc * 2;
                    af[mi][0] = *(const uint32_t*)ap;
                    af[mi][1] = *(const uint32_t*)(ap + 8 * AS_STRIDE);
                    af[mi][2] = *(const uint32_t*)(ap + 8);
                    af[mi][3] = *(const uint32_t*)(ap + 8 * AS_STRIDE + 8);
                }
                #pragma unroll
                for (int ni = 0; ni < 4; ni++) {
                    const __nv_bfloat16* bp =
                        bbh + (wn * 32 + ni * 8 + lr) * BS_STRIDE + kbb + lc * 2;
                    bhf[ni][0] = *(const uint32_t*)bp;
                    bhf[ni][1] = *(const uint32_t*)(bp + 8);
                }
                // term Ah*Bh
                #pragma unroll
                for (int mi = 0; mi < 4; mi++)
                    #pragma unroll
                    for (int ni = 0; ni < 4; ni++)
                        mma_bf16(acc[mi][ni], af[mi], bhf[ni]);

                #pragma unroll
                for (int ni = 0; ni < 4; ni++) {
                    const __nv_bfloat16* bp =
                        bbl + (wn * 32 + ni * 8 + lr) * BS_STRIDE + kbb + lc * 2;
                    blf[ni][0] = *(const uint32_t*)bp;
                    blf[ni][1] = *(const uint32_t*)(bp + 8);
                }
                // term Ah*Bl
                #pragma unroll
                for (int mi = 0; mi < 4; mi++)
                    #pragma unroll
                    for (int ni = 0; ni < 4; ni++)
                        mma_bf16(acc[mi][ni], af[mi], blf[ni]);

                #pragma unroll
                for (int mi = 0; mi < 4; mi++) {
                    const __nv_bfloat16* ap =
                        sm + SM_AL + (wm * 64 + mi * 16 + lr) * AS_STRIDE + kb + lc * 2;
                    af[mi][0] = *(const uint32_t*)ap;
                    af[mi][1] = *(const uint32_t*)(ap + 8 * AS_STRIDE);
                    af[mi][2] = *(const uint32_t*)(ap + 8);
                    af[mi][3] = *(const uint32_t*)(ap + 8 * AS_STRIDE + 8);
                }
                // term Al*Bh
                #pragma unroll
                for (int mi = 0; mi < 4; mi++)
                    #pragma unroll
                    for (int ni = 0; ni < 4; ni++)
                        mma_bf16(acc[mi][ni], af[mi], bhf[ni]);
            }

            if (c < 3) {
                __syncthreads();   // all warps done reading buf (c+1)&1 (from chunk c-1)
                // convert + store chunk c+1 into buf (c+1)&1
                __nv_bfloat16* bh = sm + SM_B + ((c + 1) & 1) * (2 * BS_SIZE)
                                    + n * BS_STRIDE + hh * 16;
                __nv_bfloat16* bl = bh + BS_SIZE;
                uint32_t ph[8], pl[8];
                #pragma unroll
                for (int j = 0; j < 8; j++) {
                    __nv_bfloat162 hp, lp;
                    hp.x = __float2bfloat16(v[2 * j]);
                    hp.y = __float2bfloat16(v[2 * j + 1]);
                    lp.x = __float2bfloat16(v[2 * j] - __bfloat162float(hp.x));
                    lp.y = __float2bfloat16(v[2 * j + 1] - __bfloat162float(hp.y));
                    ph[j] = *(uint32_t*)&hp;
                    pl[j] = *(uint32_t*)&lp;
                }
                *(uint4*)bh       = make_uint4(ph[0], ph[1], ph[2], ph[3]);
                *(uint4*)(bh + 8) = make_uint4(ph[4], ph[5], ph[6], ph[7]);
                *(uint4*)bl       = make_uint4(pl[0], pl[1], pl[2], pl[3]);
                *(uint4*)(bl + 8) = make_uint4(pl[4], pl[5], pl[6], pl[7]);
                __syncthreads();   // STS visible before next MMA
            }
        }

        // ---- epilogue: direct STG, D[o][ncol] -> out[b][o][k] ----
        #pragma unroll
        for (int ni = 0; ni < 4; ni++) {
            const int nc0 = wn * 32 + ni * 8 + lc * 2;
            const int g0 = gtile * 128 + nc0;
            const int g1 = g0 + 1;
            const int b0 = g0 / NL, k0 = g0 - b0 * NL + KOFF;
            const int b1 = g1 / NL, k1 = g1 - b1 * NL + KOFF;
            float* p0 = out + (size_t)b0 * BSTRIDE + k0;
            float* p1 = out + (size_t)b1 * BSTRIDE + k1;
            #pragma unroll
            for (int mi = 0; mi < 4; mi++) {
                const int r = wm * 64 + mi * 16 + lr;
                p0[r * NCOEF]       = acc[mi][ni][0];
                p1[r * NCOEF]       = acc[mi][ni][1];
                p0[(r + 8) * NCOEF] = acc[mi][ni][2];
                p1[(r + 8) * NCOEF] = acc[mi][ni][3];
            }
        }
        if (tt < 3) __syncthreads();   // buf0 rewrite next tile vs chunk-2 readers
    }
}

__global__ void __launch_bounds__(256, 2)
sph_hmma(const float* __restrict__ x, float* __restrict__ out) {
    extern __shared__ __align__(16) __nv_bfloat16 sm[];
    const int bid = blockIdx.x;
    if (bid < 32)       run_group<1,  0,  0>(x, out, bid,       sm);
    else if (bid < 192) run_group<5,  1,  1>(x, out, bid - 32,  sm);
    else if (bid < 480) run_group<9,  6,  2>(x, out, bid - 192, sm);
    else if (bid < 896) run_group<13, 15, 3>(x, out, bid - 480, sm);
    else                run_group<17, 28, 4>(x, out, bid - 896, sm);
}

extern "C" void kernel_launch(void* const* d_in, const int* in_sizes, int n_in,
                              void* d_out, int out_size) {
    const float* x = (const float*)d_in[0];   // [16384, 128, 45] f32
    const float* w = (const float*)d_in[1];   // [128, 128, 5]   f32
    float* out = (float*)d_out;

    cudaFuncSetAttribute(sph_hmma, cudaFuncAttributeMaxDynamicSharedMemorySize,
                         SMEM_BYTES);

    prep_w<<<160, 512>>>(w);
    sph_hmma<<<1440, 256, SMEM_BYTES>>>(x, out);
}

// round 5
// speedup vs baseline: 1.2488x; 1.0156x over previous
#include <cuda_runtime.h>
#include <cuda_bf16.h>
#include <cstdint>

// SphConv via mma.sync (HMMA) bf16 split-precision GEMM, software-pipelined.
// out[b,o,k] = (scale_l/128) * sum_i x[b,i,k] * w[o,i,l(k)/2]
// Per l-group GEMM: D[o, (b,k)] = W_l[o,i] @ X[i,(b,k)], M=K=128.
// Split bf16: D = Ah*Bh + Ah*Bl + Al*Bh (fp32 accum).

#define NCOEF 45
#define BSTRIDE (128 * NCOEF)

// smem layout in halves
#define AS_STRIDE 136                  // 272B rows: 17x16B -> ldsm conflict-free
#define BS_STRIDE 40                   // 80B rows:   5x16B -> ldsm conflict-free
#define AS_SIZE (128 * AS_STRIDE)
#define BS_SIZE (128 * BS_STRIDE)
#define SM_AH 0
#define SM_AL AS_SIZE
#define SM_B  (2 * AS_SIZE)            // [buf][prec][128][BS_STRIDE]
#define SMEM_BYTES ((2 * AS_SIZE + 4 * BS_SIZE) * 2)   // 110592

__device__ __nv_bfloat16 g_wh[5 * 128 * 128];
__device__ __nv_bfloat16 g_wl[5 * 128 * 128];

__global__ void prep_w(const float* __restrict__ w) {
    int idx = blockIdx.x * blockDim.x + threadIdx.x;  // 81920 exactly
    int l2 = idx >> 14;
    int rem = idx & 16383;
    int o = rem >> 7;
    int i = rem & 127;
    float l = 2.0f * (float)l2;
    float s = 6.28318530717958647692f *
              sqrtf(12.5663706143591729539f / (2.0f * l + 1.0f)) * (1.0f / 128.0f);
    float v = w[(o * 128 + i) * 5 + l2] * s;
    __nv_bfloat16 h = __float2bfloat16(v);
    g_wh[idx] = h;
    g_wl[idx] = __float2bfloat16(v - __bfloat162float(h));
}

__device__ __forceinline__ uint32_t smem_u32(const void* p) {
    uint32_t a;
    asm("{ .reg .u64 t; cvta.to.shared.u64 t, %1; cvt.u32.u64 %0, t; }" : "=r"(a) : "l"(p));
    return a;
}
__device__ __forceinline__ void mma_bf16(float* d, const uint32_t* a, const uint32_t* b) {
    asm volatile(
        "mma.sync.aligned.m16n8k16.row.col.f32.bf16.bf16.f32 "
        "{%0,%1,%2,%3}, {%4,%5,%6,%7}, {%8,%9}, {%0,%1,%2,%3};"
        : "+f"(d[0]), "+f"(d[1]), "+f"(d[2]), "+f"(d[3])
        : "r"(a[0]), "r"(a[1]), "r"(a[2]), "r"(a[3]), "r"(b[0]), "r"(b[1]));
}
__device__ __forceinline__ void ldsm4(uint32_t* r, uint32_t addr) {
    asm volatile("ldmatrix.sync.aligned.m8n8.x4.shared.b16 {%0,%1,%2,%3}, [%4];"
                 : "=r"(r[0]), "=r"(r[1]), "=r"(r[2]), "=r"(r[3]) : "r"(addr));
}

template <int NL, int KOFF, int L2>
__device__ __forceinline__ void run_group(const float* __restrict__ x,
                                          float* __restrict__ out,
                                          int ctaIdx, __nv_bfloat16* sm) {
    const int tid  = threadIdx.x;
    const int lane = tid & 31;
    const int wid  = tid >> 5;
    const int wm   = wid & 1;
    const int wn   = wid >> 1;
    const int lr   = lane >> 2;
    const int lc   = lane & 3;

    // ---- resident A (hi/lo weights) into smem ----
    {
        const uint4* sh = (const uint4*)(g_wh + L2 * 16384);
        const uint4* sl = (const uint4*)(g_wl + L2 * 16384);
        #pragma unroll
        for (int it = 0; it < 8; it++) {
            int v4 = it * 256 + tid;
            int r  = v4 >> 4, c8 = v4 & 15;
            *(uint4*)(sm + SM_AH + r * AS_STRIDE + c8 * 8) = sh[v4];
            *(uint4*)(sm + SM_AL + r * AS_STRIDE + c8 * 8) = sl[v4];
        }
    }

    const int n  = tid & 127;
    const int hh = tid >> 7;
    const uint32_t sbase = smem_u32(sm);

    // ldmatrix lane addresses (bytes)
    const uint32_t aAh = sbase + 2 * (SM_AH + (wm * 64 + (lane & 15)) * AS_STRIDE
                                      + ((lane >> 4) << 3));
    const uint32_t aB0 = sbase + 2 * (SM_B + (wn * 32 + (lane & 7) + ((lane >> 4) << 3))
                                      * BS_STRIDE + (((lane >> 3) & 1) << 3));

    // per-chunk x loader: v[j] = x[b][c*32+hh*16+j][k]
    auto ldv = [&](float* v, int gtile, int c) {
        const int gn = gtile * 128 + n;
        const int b  = gn / NL;
        const int kk = gn - b * NL + KOFF;
        const float* xcol = x + (size_t)b * BSTRIDE + kk + (size_t)(c * 32 + hh * 16) * NCOEF;
        #pragma unroll
        for (int j = 0; j < 16; j++) v[j] = xcol[j * NCOEF];
    };
    // convert + STS chunk into buf
    auto stsv = [&](const float* v, int buf) {
        __nv_bfloat16* bh = sm + SM_B + buf * (2 * BS_SIZE) + n * BS_STRIDE + hh * 16;
        __nv_bfloat16* bl = bh + BS_SIZE;
        uint32_t ph[8], pl[8];
        #pragma unroll
        for (int j = 0; j < 8; j++) {
            __nv_bfloat162 hp, lp;
            hp.x = __float2bfloat16(v[2 * j]);
            hp.y = __float2bfloat16(v[2 * j + 1]);
            lp.x = __float2bfloat16(v[2 * j] - __bfloat162float(hp.x));
            lp.y = __float2bfloat16(v[2 * j + 1] - __bfloat162float(hp.y));
            ph[j] = *(uint32_t*)&hp;
            pl[j] = *(uint32_t*)&lp;
        }
        *(uint4*)bh       = make_uint4(ph[0], ph[1], ph[2], ph[3]);
        *(uint4*)(bh + 8) = make_uint4(ph[4], ph[5], ph[6], ph[7]);
        *(uint4*)bl       = make_uint4(pl[0], pl[1], pl[2], pl[3]);
        *(uint4*)(bl + 8) = make_uint4(pl[4], pl[5], pl[6], pl[7]);
    };

    float acc[4][4][4];
    #pragma unroll
    for (int mi = 0; mi < 4; mi++)
        #pragma unroll
        for (int ni = 0; ni < 4; ni++)
            #pragma unroll
            for (int q = 0; q < 4; q++) acc[mi][ni][q] = 0.0f;

    float v[16];
    // prologue: chunk0 -> buf0, start chunk1
    ldv(v, ctaIdx * 4, 0);
    stsv(v, 0);
    ldv(v, ctaIdx * 4, 1);

    for (int tt = 0; tt < 4; tt++) {
        const int gtile = ctaIdx * 4 + tt;
        const bool last = (tt == 3);

        #pragma unroll
        for (int c = 0; c < 4; c++) {
            __syncthreads();
            // STS chunk (c+1): for c==3 this is next tile's chunk 0 -> buf0
            if (c < 3)        stsv(v, (c + 1) & 1);
            else if (!last)   stsv(v, 0);
            // LDG chunk (c+2)
            if (c < 2)        ldv(v, gtile, c + 2);
            else if (!last)   ldv(v, gtile + 1, c - 2);

            // ---- MMA on buf c&1 ----
            const uint32_t bufB = aB0 + (uint32_t)((c & 1) * (4 * BS_SIZE));

            #pragma unroll
            for (int ks = 0; ks < 2; ks++) {
                const uint32_t kbA = (uint32_t)((c * 32 + ks * 16) * 2);
                const uint32_t kbB = (uint32_t)(ks * 32);

                uint32_t ah[4][4], bh[2][4], bl[2][4];
                #pragma unroll
                for (int mi = 0; mi < 4; mi++)
                    ldsm4(ah[mi], aAh + (uint32_t)(mi * 16 * AS_STRIDE * 2) + kbA);
                #pragma unroll
                for (int p = 0; p < 2; p++)
                    ldsm4(bh[p], bufB + (uint32_t)(p * 16 * BS_STRIDE * 2) + kbB);
                #pragma unroll
                for (int p = 0; p < 2; p++)
                    ldsm4(bl[p], bufB + (uint32_t)(BS_SIZE * 2)
                                 + (uint32_t)(p * 16 * BS_STRIDE * 2) + kbB);

                #pragma unroll
                for (int mi = 0; mi < 4; mi++)
                    #pragma unroll
                    for (int ni = 0; ni < 4; ni++)
                        mma_bf16(acc[mi][ni], ah[mi], &bh[ni >> 1][(ni & 1) * 2]);
                #pragma unroll
                for (int mi = 0; mi < 4; mi++)
                    #pragma unroll
                    for (int ni = 0; ni < 4; ni++)
                        mma_bf16(acc[mi][ni], ah[mi], &bl[ni >> 1][(ni & 1) * 2]);

                uint32_t al[4][4];
                #pragma unroll
                for (int mi = 0; mi < 4; mi++)
                    ldsm4(al[mi], aAh + (uint32_t)(AS_SIZE * 2)
                                  + (uint32_t)(mi * 16 * AS_STRIDE * 2) + kbA);
                #pragma unroll
                for (int mi = 0; mi < 4; mi++)
                    #pragma unroll
                    for (int ni = 0; ni < 4; ni++)
                        mma_bf16(acc[mi][ni], al[mi], &bh[ni >> 1][(ni & 1) * 2]);
            }
        }

        // ---- epilogue: direct STG ----
        #pragma unroll
        for (int ni = 0; ni < 4; ni++) {
            const int nc0 = wn * 32 + ni * 8 + lc * 2;
            const int g0 = gtile * 128 + nc0;
            const int g1 = g0 + 1;
            const int b0 = g0 / NL, k0 = g0 - b0 * NL + KOFF;
            const int b1 = g1 / NL, k1 = g1 - b1 * NL + KOFF;
            float* p0 = out + (size_t)b0 * BSTRIDE + k0;
            float* p1 = out + (size_t)b1 * BSTRIDE + k1;
            #pragma unroll
            for (int mi = 0; mi < 4; mi++) {
                const int r = wm * 64 + mi * 16 + lr;
                p0[r * NCOEF]       = acc[mi][ni][0];
                p1[r * NCOEF]       = acc[mi][ni][1];
                p0[(r + 8) * NCOEF] = acc[mi][ni][2];
                p1[(r + 8) * NCOEF] = acc[mi][ni][3];
            }
        }
        if (!last) {
            #pragma unroll
            for (int mi = 0; mi < 4; mi++)
                #pragma unroll
                for (int ni = 0; ni < 4; ni++)
                    #pragma unroll
                    for (int q = 0; q < 4; q++) acc[mi][ni][q] = 0.0f;
        }
    }
}

__global__ void __launch_bounds__(256, 2)
sph_hmma(const float* __restrict__ x, float* __restrict__ out) {
    extern __shared__ __align__(16) __nv_bfloat16 sm[];
    const int bid = blockIdx.x;
    if (bid < 32)       run_group<1,  0,  0>(x, out, bid,       sm);
    else if (bid < 192) run_group<5,  1,  1>(x, out, bid - 32,  sm);
    else if (bid < 480) run_group<9,  6,  2>(x, out, bid - 192, sm);
    else if (bid < 896) run_group<13, 15, 3>(x, out, bid - 480, sm);
    else                run_group<17, 28, 4>(x, out, bid - 896, sm);
}

extern "C" void kernel_launch(void* const* d_in, const int* in_sizes, int n_in,
                              void* d_out, int out_size) {
    const float* x = (const float*)d_in[0];   // [16384, 128, 45] f32
    const float* w = (const float*)d_in[1];   // [128, 128, 5]   f32
    float* out = (float*)d_out;

    cudaFuncSetAttribute(sph_hmma, cudaFuncAttributeMaxDynamicSharedMemorySize,
                         SMEM_BYTES);

    prep_w<<<160, 512>>>(w);
    sph_hmma<<<1440, 256, SMEM_BYTES>>>(x, out);
}

// round 6
// speedup vs baseline: 1.9006x; 1.5219x over previous
#include <cuda_runtime.h>
#include <cstdint>

// SphConv via tf32 mma.sync with dense fused-(b,k) columns.
// out[b,o,k] = (scale_l/128) * sum_i x[b,i,k] * w[o,i,l(k)/2]
// CTA: 2 batches x 45 k (padded 48) x 128 o.  K = 128 (i), one-shot cp.async tile.
// l-group boundaries: recompute boundary n8 blocks per group, predicated stores.

#define NCOEF 45
#define BSTRIDE (128 * NCOEF)     // 5760
#define BS_ROW 104                // 96 data cols (2 x 48) + 8 pad floats
#define SMEM_BYTES (128 * BS_ROW * 4)   // 53248

// Packed tf32 weights in m16n8k8 A-fragment order, scale folded:
// wp[((lg*16 + ks)*8 + mb)*32 + lane] = float4{ W(m,k), W(m+8,k), W(m,k+4), W(m+8,k+4) }
// with m = mb*16 + (lane>>2), k = ks*8 + (lane&3).
__device__ float4 g_wp[5 * 16 * 8 * 32];

__global__ void prep_w(const float* __restrict__ w) {
    int idx  = blockIdx.x * blockDim.x + threadIdx.x;   // 20480 exactly
    int lane = idx & 31;
    int mb   = (idx >> 5) & 7;
    int s    = (idx >> 8) & 15;
    int lg   = idx >> 12;                                // 0..4
    int m = mb * 16 + (lane >> 2);
    int k = s * 8 + (lane & 3);
    float l = 2.0f * (float)lg;
    float sc = 6.28318530717958647692f *
               sqrtf(12.5663706143591729539f / (2.0f * l + 1.0f)) * (1.0f / 128.0f);
    float4 v;
    v.x = w[(m * 128 + k) * 5 + lg] * sc;
    v.y = w[((m + 8) * 128 + k) * 5 + lg] * sc;
    v.z = w[(m * 128 + k + 4) * 5 + lg] * sc;
    v.w = w[((m + 8) * 128 + k + 4) * 5 + lg] * sc;
    // round to tf32 (rna) so MMA truncation is exact
    asm("cvt.rna.tf32.f32 %0, %0;" : "+f"(v.x));
    asm("cvt.rna.tf32.f32 %0, %0;" : "+f"(v.y));
    asm("cvt.rna.tf32.f32 %0, %0;" : "+f"(v.z));
    asm("cvt.rna.tf32.f32 %0, %0;" : "+f"(v.w));
    g_wp[idx] = v;
}

__device__ __forceinline__ uint32_t smem_u32(const void* p) {
    uint32_t a;
    asm("{ .reg .u64 t; cvta.to.shared.u64 t, %1; cvt.u32.u64 %0, t; }" : "=r"(a) : "l"(p));
    return a;
}
__device__ __forceinline__ void mma_tf32(float* d, const float4& a,
                                         uint32_t b0, uint32_t b1) {
    asm volatile(
        "mma.sync.aligned.m16n8k8.row.col.f32.tf32.tf32.f32 "
        "{%0,%1,%2,%3}, {%4,%5,%6,%7}, {%8,%9}, {%0,%1,%2,%3};"
        : "+f"(d[0]), "+f"(d[1]), "+f"(d[2]), "+f"(d[3])
        : "r"(__float_as_uint(a.x)), "r"(__float_as_uint(a.y)),
          "r"(__float_as_uint(a.z)), "r"(__float_as_uint(a.w)),
          "r"(b0), "r"(b1));
}

__global__ void __launch_bounds__(256)
sph_tf32(const float* __restrict__ x, float* __restrict__ out) {
    extern __shared__ __align__(16) float Bs[];   // [128][BS_ROW]
    const int tid = threadIdx.x;
    const uint32_t sbase = smem_u32(Bs);

    // ---- zero pad columns (45..47 per batch; row-pad never read) ----
    #pragma unroll
    for (int t = 0; t < 3; t++) {
        int idx = t * 256 + tid;        // 768 pad words
        int row = idx / 6, wh = idx % 6;
        int col = (wh < 3) ? (45 + wh) : (93 + wh - 3);
        Bs[row * BS_ROW + col] = 0.0f;
    }

    // ---- one-shot cp.async tile load: CTA's x region is CONTIGUOUS ----
    // e = t*256 + tid indexes 11520 floats = x[(bG..bG+1)][0:128][0:45]
    {
        const float* src = x + (size_t)blockIdx.x * 2 * BSTRIDE + tid;
        // decompose e = b_l*5760 + i*45 + k incrementally
        int k = tid % 45;
        int i = (tid / 45) & 127;           // tid<256 -> b_l=0 initially... tid/45 <= 5
        int b_l = 0;
        #pragma unroll 1
        for (int t = 0; t < 45; t++) {
            uint32_t dst = sbase + (uint32_t)(i * BS_ROW + b_l * 48 + k) * 4u;
            asm volatile("cp.async.ca.shared.global [%0], [%1], 4;"
                         :: "r"(dst), "l"(src + (size_t)t * 256) : "memory");
            // advance e by 256 = 5*45 + 31
            k += 31; i += 5;
            if (k >= 45) { k -= 45; i += 1; }
            if (i >= 128) { i -= 128; b_l = 1; }
        }
        asm volatile("cp.async.commit_group;" ::: "memory");
        asm volatile("cp.async.wait_group 0;" ::: "memory");
    }
    __syncthreads();

    // ---- compute ----
    const int lane = tid & 31, wid = tid >> 5;
    const int wm = wid & 1;            // m-half (o 0-63 / 64-127)
    const int b_l = (wid >> 1) & 1;    // batch within CTA
    const int P = wid >> 2;            // pass-split
    const int lr = lane >> 2, lc = lane & 3;

    // pass tables: (block, l-group); blocks are 8-col groups within 48-padded k
    const int blkT[2][5] = {{0, 0, 1, 3, 4}, {0, 1, 2, 3, 5}};
    const int lgT [2][5] = {{0, 2, 3, 3, 4}, {1, 2, 3, 4, 4}};
    const int glo[5] = {0, 1, 6, 15, 28};
    const int ghi[5] = {1, 6, 15, 28, 45};

    float* obase = out + ((size_t)blockIdx.x * 2 + b_l) * BSTRIDE;

    #pragma unroll 1
    for (int p = 0; p < 5; p++) {
        const int blk = blkT[P][p], lg = lgT[P][p];
        const int n0 = b_l * 48 + blk * 8 + lr;    // smem col for B frags
        const int cA = blk * 8 + lc * 2;           // out k for c0/c2
        const bool s0 = (cA >= glo[lg]) && (cA < ghi[lg]);
        const bool s1 = (cA + 1 >= glo[lg]) && (cA + 1 < ghi[lg]);

        #pragma unroll
        for (int g = 0; g < 2; g++) {
            const int mb0 = wm * 4 + g * 2;
            const int aIdx = (lg * 16 * 8 + mb0) * 32 + lane;  // ks stride 256
            float4 a0c = g_wp[aIdx],       a1c = g_wp[aIdx + 32];
            float4 a0n = g_wp[aIdx + 256], a1n = g_wp[aIdx + 288];
            float acc0[4] = {0, 0, 0, 0}, acc1[4] = {0, 0, 0, 0};

            #pragma unroll
            for (int ks = 0; ks < 16; ks++) {
                float bf0 = Bs[(ks * 8 + lc) * BS_ROW + n0];
                float bf1 = Bs[(ks * 8 + lc + 4) * BS_ROW + n0];
                uint32_t b0, b1;
                asm("cvt.rna.tf32.f32 %0, %1;" : "=r"(b0) : "f"(bf0));
                asm("cvt.rna.tf32.f32 %0, %1;" : "=r"(b1) : "f"(bf1));
                mma_tf32(acc0, a0c, b0, b1);
                mma_tf32(acc1, a1c, b0, b1);
                a0c = a0n; a1c = a1n;
                if (ks < 14) {
                    a0n = g_wp[aIdx + (ks + 2) * 256];
                    a1n = g_wp[aIdx + (ks + 2) * 256 + 32];
                }
            }

            // predicated stores: rows mb*16+lr (+8), cols cA, cA+1
            {
                float* q = obase + (size_t)(mb0 * 16 + lr) * NCOEF;
                if (s0) q[cA]     = acc0[0];
                if (s1) q[cA + 1] = acc0[1];
                if (s0) q[cA + 8 * NCOEF]     = acc0[2];
                if (s1) q[cA + 1 + 8 * NCOEF] = acc0[3];
                q += 16 * NCOEF;
                if (s0) q[cA]     = acc1[0];
                if (s1) q[cA + 1] = acc1[1];
                if (s0) q[cA + 8 * NCOEF]     = acc1[2];
                if (s1) q[cA + 1 + 8 * NCOEF] = acc1[3];
            }
        }
    }
}

extern "C" void kernel_launch(void* const* d_in, const int* in_sizes, int n_in,
                              void* d_out, int out_size) {
    const float* x = (const float*)d_in[0];   // [16384, 128, 45] f32
    const float* w = (const float*)d_in[1];   // [128, 128, 5]   f32
    float* out = (float*)d_out;

    cudaFuncSetAttribute(sph_tf32, cudaFuncAttributeMaxDynamicSharedMemorySize,
                         SMEM_BYTES);

    prep_w<<<80, 256>>>(w);
    sph_tf32<<<8192, 256, SMEM_BYTES>>>(x, out);   // 2 batches per CTA
}